// round 3
// baseline (speedup 1.0000x reference)
#include <cuda_runtime.h>
#include <cstdint>

#define NV_P   32
#define C_VX   0.16f
#define C_VY   0.16f
#define C_VZ   4.0f
#define C_XOFF 0.08f
#define C_YOFF -39.6f
#define C_ZOFF -1.0f
#define BN_EPS 1e-3f

#define K1_BLOCKS 740
#define K1_THREADS 128
#define K3_BLOCKS 1036
#define K3_THREADS 128
#define NSTAT 70   // 10 mean (packed order = natural) + 60 (30 packed S pairs)

// -------- global scratch (allocation-free rule: __device__ globals) --------
__device__ float  g_part[K1_BLOCKS * NSTAT];
__device__ double g_stat[NSTAT];
__device__ float  g_ab[128];                 // a[0..63], b[64..127]
__device__ float4 g_mean[131072];            // per-voxel xyz mean (V<=131072)

// ---------------- packed f32x2 helpers ----------------
__device__ __forceinline__ unsigned long long pk2(float lo, float hi) {
    unsigned long long r;
    asm("mov.b64 %0, {%1, %2};" : "=l"(r) : "f"(lo), "f"(hi));
    return r;
}
__device__ __forceinline__ void unpk2(unsigned long long x, float& lo, float& hi) {
    asm("mov.b64 {%0, %1}, %2;" : "=f"(lo), "=f"(hi) : "l"(x));
}
__device__ __forceinline__ unsigned long long fma2(unsigned long long a, unsigned long long b, unsigned long long c) {
    unsigned long long d;
    asm("fma.rn.f32x2 %0, %1, %2, %3;" : "=l"(d) : "l"(a), "l"(b), "l"(c));
    return d;
}
__device__ __forceinline__ unsigned long long add2(unsigned long long a, unsigned long long b) {
    unsigned long long d;
    asm("add.rn.f32x2 %0, %1, %2;" : "=l"(d) : "l"(a), "l"(b));
    return d;
}
__device__ __forceinline__ unsigned long long mul2(unsigned long long a, unsigned long long b) {
    unsigned long long d;
    asm("mul.rn.f32x2 %0, %1, %2;" : "=l"(d) : "l"(a), "l"(b));
    return d;
}
__device__ __forceinline__ void wred3(float& a, float& b, float& c) {
#pragma unroll
    for (int off = 16; off; off >>= 1) {
        a += __shfl_xor_sync(0xffffffffu, a, off);
        b += __shfl_xor_sync(0xffffffffu, b, off);
        c += __shfl_xor_sync(0xffffffffu, c, off);
    }
}

// ---------------- k1: feature moments (packed), per-block partials, voxel means ----------------
__global__ __launch_bounds__(K1_THREADS) void k1_stats(
    const float* __restrict__ vf, const int* __restrict__ vnp,
    const int* __restrict__ coords, int V)
{
    unsigned long long SP[30];     // packed S: for i in 0..9, j2 in i/2..4 -> (f_i*f_{2j2}, f_i*f_{2j2+1})
    unsigned long long mp[5];      // packed m: (f0,f1),(f2,f3),(f4,f5),(f6,f7),(f8,f9)
#pragma unroll
    for (int i = 0; i < 30; i++) SP[i] = 0ull;
#pragma unroll
    for (int i = 0; i < 5; i++) mp[i] = 0ull;

    const int lane = threadIdx.x & 31;
    const int wib  = threadIdx.x >> 5;
    const int gw   = (blockIdx.x * blockDim.x + threadIdx.x) >> 5;
    const int nw   = (gridDim.x * blockDim.x) >> 5;

    // depth-2 software pipeline
    float4 ptA, ptB; int cntA = 0, cntB = 0; int4 cA, cB;
    int v = gw;
    if (v < V) {
        ptA = reinterpret_cast<const float4*>(vf)[v * NV_P + lane];
        cntA = vnp[v];
        cA = reinterpret_cast<const int4*>(coords)[v];
    }
    if (v + nw < V) {
        ptB = reinterpret_cast<const float4*>(vf)[(v + nw) * NV_P + lane];
        cntB = vnp[v + nw];
        cB = reinterpret_cast<const int4*>(coords)[v + nw];
    }

    while (v < V) {
        int v2 = v + 2 * nw;
        float4 ptC; int cntC = 0; int4 cC;
        if (v2 < V) {
            ptC = reinterpret_cast<const float4*>(vf)[v2 * NV_P + lane];
            cntC = vnp[v2];
            cC = reinterpret_cast<const int4*>(coords)[v2];
        }

        // ---- process voxel v (ptA/cntA/cA) ----
        {
            float sx = ptA.x, sy = ptA.y, sz = ptA.z;
            wred3(sx, sy, sz);                    // sum over all 32 points (matches ref)
            float inv = 1.0f / (float)cntA;
            float mx = sx * inv, my = sy * inv, mz = sz * inv;
            if (lane == 0) g_mean[v] = make_float4(mx, my, mz, 0.f);
            float cx = (float)cA.w * C_VX + C_XOFF;
            float cy = (float)cA.z * C_VY + C_YOFF;
            float cz = (float)cA.y * C_VZ + C_ZOFF;

            if (lane < cntA) {
                float f[10];
                f[0] = ptA.x; f[1] = ptA.y; f[2] = ptA.z; f[3] = ptA.w;
                f[4] = ptA.x - mx; f[5] = ptA.y - my;
                f[6] = ptA.z - mz; f[7] = ptA.x - cx;
                f[8] = ptA.y - cy; f[9] = ptA.z - cz;
                unsigned long long g[5];
                g[0] = pk2(f[0], f[1]); g[1] = pk2(f[2], f[3]);
                g[2] = pk2(f[4], f[5]); g[3] = pk2(f[6], f[7]);
                g[4] = pk2(f[8], f[9]);
#pragma unroll
                for (int k = 0; k < 5; k++) mp[k] = add2(mp[k], g[k]);
                int idx = 0;
#pragma unroll
                for (int i = 0; i < 10; i++) {
                    unsigned long long bi = pk2(f[i], f[i]);
#pragma unroll
                    for (int j2 = i / 2; j2 < 5; j2++) { SP[idx] = fma2(bi, g[j2], SP[idx]); idx++; }
                }
            }
        }

        ptA = ptB; cntA = cntB; cA = cB;
        ptB = ptC; cntB = cntC; cB = cC;
        v += nw;
    }

    // warp butterfly on packed accumulators (64-bit shfl)
#pragma unroll
    for (int k = 0; k < 5; k++)
#pragma unroll
        for (int off = 16; off; off >>= 1)
            mp[k] = add2(mp[k], __shfl_xor_sync(0xffffffffu, mp[k], off));
#pragma unroll
    for (int n = 0; n < 30; n++)
#pragma unroll
        for (int off = 16; off; off >>= 1)
            SP[n] = add2(SP[n], __shfl_xor_sync(0xffffffffu, SP[n], off));

    __shared__ float red[4 * NSTAT];
    if (lane == 0) {
#pragma unroll
        for (int k = 0; k < 5; k++) {
            float lo, hi; unpk2(mp[k], lo, hi);
            red[wib * NSTAT + 2 * k] = lo; red[wib * NSTAT + 2 * k + 1] = hi;
        }
#pragma unroll
        for (int n = 0; n < 30; n++) {
            float lo, hi; unpk2(SP[n], lo, hi);
            red[wib * NSTAT + 10 + 2 * n] = lo; red[wib * NSTAT + 10 + 2 * n + 1] = hi;
        }
    }
    __syncthreads();
    int t = threadIdx.x;
    if (t < NSTAT) {
        float s = 0.f;
#pragma unroll
        for (int w = 0; w < 4; w++) s += red[w * NSTAT + t];
        g_part[blockIdx.x * NSTAT + t] = s;
    }
}

// ---------------- kred: reduce per-block partials (double) ----------------
__global__ void kred_stats() {
    int b = blockIdx.x;                 // one stat per block, 70 blocks
    double s = 0.0;
    for (int i = threadIdx.x; i < K1_BLOCKS; i += blockDim.x)
        s += (double)g_part[i * NSTAT + b];
    __shared__ double sd[256];
    sd[threadIdx.x] = s;
    __syncthreads();
    for (int off = 128; off; off >>= 1) {
        if (threadIdx.x < off) sd[threadIdx.x] += sd[threadIdx.x + off];
        __syncthreads();
    }
    if (threadIdx.x == 0) g_stat[b] = sd[0];
}

// ---------------- k2: fold BN into per-channel a,b ----------------
__global__ void k2_coef(const float* __restrict__ W, const float* __restrict__ gamma,
                        const float* __restrict__ beta, double invN)
{
    int o = threadIdx.x;
    if (o >= 64) return;
    double w[10];
#pragma unroll
    for (int c = 0; c < 10; c++) w[c] = (double)W[o * 10 + c];
    double mean = 0.0;
#pragma unroll
    for (int c = 0; c < 10; c++) mean += w[c] * g_stat[c];
    mean *= invN;
    double e2 = 0.0;
    int idx = 0;
#pragma unroll
    for (int i = 0; i < 10; i++) {
#pragma unroll
        for (int j2 = i / 2; j2 < 5; j2++) {
#pragma unroll
            for (int lsel = 0; lsel < 2; lsel++) {
                int j = 2 * j2 + lsel;
                double Sv = g_stat[10 + idx * 2 + lsel];
                double coef = (j == i) ? 1.0 : (((i ^ j) == 1) ? 1.0 : 2.0);
                e2 += coef * w[i] * w[j] * Sv;
            }
            idx++;
        }
    }
    e2 *= invN;
    double var = e2 - mean * mean;
    float a = gamma[o] * rsqrtf((float)var + BN_EPS);
    float b = beta[o] - (float)mean * a;
    g_ab[o]      = a;
    g_ab[64 + o] = b;
}

// ---------------- k3: per-voxel base-free max of s*(u.p), epilogue affine+relu ----------------
__global__ __launch_bounds__(K3_THREADS) void k3_out(
    const float* __restrict__ vf, const int* __restrict__ vnp,
    const int* __restrict__ coords, const float* __restrict__ W,
    float* __restrict__ out, int V)
{
    __shared__ __align__(16) float sh[4 * NV_P * 8];   // 4 warps * 32 pts * 8 floats
    const int lane = threadIdx.x & 31;
    const int wib  = threadIdx.x >> 5;
    const int gw   = (blockIdx.x * blockDim.x + threadIdx.x) >> 5;
    const int nw   = (gridDim.x * blockDim.x) >> 5;
    float* msh = sh + wib * (NV_P * 8);

    // lane owns output channels (2*lane, 2*lane+1)
    unsigned long long wp[10];
#pragma unroll
    for (int c = 0; c < 10; c++)
        wp[c] = pk2(W[(2 * lane) * 10 + c], W[(2 * lane + 1) * 10 + c]);
    unsigned long long u0 = add2(add2(wp[0], wp[4]), wp[7]);
    unsigned long long u1 = add2(add2(wp[1], wp[5]), wp[8]);
    unsigned long long u2 = add2(add2(wp[2], wp[6]), wp[9]);
    unsigned long long u3 = wp[3];

    float2 av = reinterpret_cast<const float2*>(g_ab)[lane];
    float2 bv = reinterpret_cast<const float2*>(g_ab + 64)[lane];
    // sign fold: track max of s*x only; out = relu(|a|*M + b)
    float s0 = (av.x >= 0.f) ? 1.f : -1.f;
    float s1 = (av.y >= 0.f) ? 1.f : -1.f;
    unsigned long long spk = pk2(s0, s1);
    u0 = mul2(u0, spk); u1 = mul2(u1, spk); u2 = mul2(u2, spk); u3 = mul2(u3, spk);
    unsigned long long ws4 = mul2(wp[4], spk), ws5 = mul2(wp[5], spk), ws6 = mul2(wp[6], spk);
    unsigned long long ws7 = mul2(wp[7], spk), ws8 = mul2(wp[8], spk), ws9 = mul2(wp[9], spk);
    float aax = fabsf(av.x), aay = fabsf(av.y);

    // depth-1 prefetch pipeline
    int v = gw;
    float4 pt, mn; int cnt; int4 c4;
    if (v < V) {
        pt  = reinterpret_cast<const float4*>(vf)[v * NV_P + lane];
        cnt = vnp[v];
        c4  = reinterpret_cast<const int4*>(coords)[v];
        mn  = g_mean[v];
    }
    while (v < V) {
        int vn = v + nw;
        float4 ptn, mnn; int cntn; int4 c4n;
        if (vn < V) {
            ptn  = reinterpret_cast<const float4*>(vf)[vn * NV_P + lane];
            cntn = vnp[vn];
            c4n  = reinterpret_cast<const int4*>(coords)[vn];
            mnn  = g_mean[vn];
        }

        // stage duplicated point data: (x,x,y,y),(z,z,w,w) -> broadcast LDS.128 yields f32x2 pairs
        __syncwarp();
        float4* sp = reinterpret_cast<float4*>(msh + lane * 8);
        sp[0] = make_float4(pt.x, pt.x, pt.y, pt.y);
        sp[1] = make_float4(pt.z, pt.z, pt.w, pt.w);
        __syncwarp();

        // base = s * ( -(mean . w[4:7]) - (center . w[7:10]) )  [independent of the loop below]
        float ncx = -((float)c4.w * C_VX + C_XOFF);
        float ncy = -((float)c4.z * C_VY + C_YOFF);
        float ncz = -((float)c4.y * C_VZ + C_ZOFF);
        unsigned long long base = mul2(pk2(-mn.x, -mn.x), ws4);
        base = fma2(pk2(-mn.y, -mn.y), ws5, base);
        base = fma2(pk2(-mn.z, -mn.z), ws6, base);
        base = fma2(pk2(ncx, ncx), ws7, base);
        base = fma2(pk2(ncy, ncy), ws8, base);
        base = fma2(pk2(ncz, ncz), ws9, base);

        // two independent max chains over y_p = s*(u . p)
        float mAlo = -3.402823466e38f, mAhi = -3.402823466e38f;
        float mBlo = -3.402823466e38f, mBhi = -3.402823466e38f;
        const ulonglong2* pp = reinterpret_cast<const ulonglong2*>(msh);
        int p = 0;
        for (; p + 2 <= cnt; p += 2) {
            ulonglong2 q0 = pp[2 * p],     r0 = pp[2 * p + 1];
            ulonglong2 q1 = pp[2 * p + 2], r1 = pp[2 * p + 3];
            unsigned long long t0 = mul2(q0.x, u0);
            unsigned long long t1 = mul2(q1.x, u0);
            t0 = fma2(q0.y, u1, t0);  t1 = fma2(q1.y, u1, t1);
            t0 = fma2(r0.x, u2, t0);  t1 = fma2(r1.x, u2, t1);
            t0 = fma2(r0.y, u3, t0);  t1 = fma2(r1.y, u3, t1);
            float lo, hi;
            unpk2(t0, lo, hi); mAlo = fmaxf(mAlo, lo); mAhi = fmaxf(mAhi, hi);
            unpk2(t1, lo, hi); mBlo = fmaxf(mBlo, lo); mBhi = fmaxf(mBhi, hi);
        }
        if (p < cnt) {
            ulonglong2 q0 = pp[2 * p], r0 = pp[2 * p + 1];
            unsigned long long t0 = mul2(q0.x, u0);
            t0 = fma2(q0.y, u1, t0);
            t0 = fma2(r0.x, u2, t0);
            t0 = fma2(r0.y, u3, t0);
            float lo, hi;
            unpk2(t0, lo, hi); mAlo = fmaxf(mAlo, lo); mAhi = fmaxf(mAhi, hi);
        }
        float blo, bhi; unpk2(base, blo, bhi);
        float Mlo = fmaxf(mAlo, mBlo) + blo;
        float Mhi = fmaxf(mAhi, mBhi) + bhi;
        if (cnt < NV_P) { Mlo = fmaxf(Mlo, 0.f); Mhi = fmaxf(Mhi, 0.f); }  // masked points: raw x = 0
        float r0o = fmaxf(fmaf(aax, Mlo, bv.x), 0.f);
        float r1o = fmaxf(fmaf(aay, Mhi, bv.y), 0.f);
        reinterpret_cast<float2*>(out)[v * 32 + lane] = make_float2(r0o, r1o);

        v = vn; pt = ptn; cnt = cntn; c4 = c4n; mn = mnn;
    }
}

extern "C" void kernel_launch(void* const* d_in, const int* in_sizes, int n_in,
                              void* d_out, int out_size) {
    const float* vf     = (const float*)d_in[0];
    const int*   vnp    = (const int*)d_in[1];
    const int*   coords = (const int*)d_in[2];
    const float* W      = (const float*)d_in[3];
    const float* gamma  = (const float*)d_in[4];
    const float* beta   = (const float*)d_in[5];
    float* out = (float*)d_out;
    int V = in_sizes[1];   // voxel_num_points element count

    k1_stats<<<K1_BLOCKS, K1_THREADS>>>(vf, vnp, coords, V);
    kred_stats<<<NSTAT, 256>>>();
    double invN = 1.0 / ((double)V * (double)NV_P);
    k2_coef<<<1, 64>>>(W, gamma, beta, invN);
    k3_out<<<K3_BLOCKS, K3_THREADS>>>(vf, vnp, coords, W, out, V);
}

// round 5
// speedup vs baseline: 1.2118x; 1.2118x over previous
#include <cuda_runtime.h>
#include <cstdint>

#define NV_P   32
#define C_VX   0.16f
#define C_VY   0.16f
#define C_VZ   4.0f
#define C_XOFF 0.08f
#define C_YOFF -39.6f
#define C_ZOFF -1.0f
#define BN_EPS 1e-3f

#define K1_BLOCKS 592
#define K1_THREADS 256
#define K3_BLOCKS 592
#define K3_THREADS 256
#define NSTAT 65   // 10 mean + 55 upper-tri S (natural order)

// -------- global scratch (allocation-free rule: __device__ globals) --------
__device__ float  g_part[NSTAT * K1_BLOCKS];   // transposed: [stat][block] for coalesced kred
__device__ double g_stat[NSTAT];
__device__ float  g_ab[128];                   // a[0..63], b[64..127]
__device__ float4 g_mc4[131072];               // per-voxel (mx,my,mz,cx)
__device__ float2 g_c2[131072];                // per-voxel (cy,cz)

// ---------------- packed f32x2 helpers ----------------
__device__ __forceinline__ unsigned long long pk2(float lo, float hi) {
    unsigned long long r;
    asm("mov.b64 %0, {%1, %2};" : "=l"(r) : "f"(lo), "f"(hi));
    return r;
}
__device__ __forceinline__ void unpk2(unsigned long long x, float& lo, float& hi) {
    asm("mov.b64 {%0, %1}, %2;" : "=f"(lo), "=f"(hi) : "l"(x));
}
__device__ __forceinline__ unsigned long long fma2(unsigned long long a, unsigned long long b, unsigned long long c) {
    unsigned long long d;
    asm("fma.rn.f32x2 %0, %1, %2, %3;" : "=l"(d) : "l"(a), "l"(b), "l"(c));
    return d;
}
__device__ __forceinline__ unsigned long long add2(unsigned long long a, unsigned long long b) {
    unsigned long long d;
    asm("add.rn.f32x2 %0, %1, %2;" : "=l"(d) : "l"(a), "l"(b));
    return d;
}
__device__ __forceinline__ unsigned long long mul2(unsigned long long a, unsigned long long b) {
    unsigned long long d;
    asm("mul.rn.f32x2 %0, %1, %2;" : "=l"(d) : "l"(a), "l"(b));
    return d;
}
__device__ __forceinline__ void wred3(float& a, float& b, float& c) {
#pragma unroll
    for (int off = 16; off; off >>= 1) {
        a += __shfl_xor_sync(0xffffffffu, a, off);
        b += __shfl_xor_sync(0xffffffffu, b, off);
        c += __shfl_xor_sync(0xffffffffu, c, off);
    }
}

// ---------------- k1: feature moments (scalar accumulators, per-block partials) ----------------
__global__ __launch_bounds__(K1_THREADS) void k1_stats(
    const float* __restrict__ vf, const int* __restrict__ vnp,
    const int* __restrict__ coords, int V)
{
    float m[10], S[55];
#pragma unroll
    for (int i = 0; i < 10; i++) m[i] = 0.f;
#pragma unroll
    for (int i = 0; i < 55; i++) S[i] = 0.f;

    const int lane = threadIdx.x & 31;
    const int wib  = threadIdx.x >> 5;
    const int gw   = (blockIdx.x * blockDim.x + threadIdx.x) >> 5;
    const int nw   = (gridDim.x * blockDim.x) >> 5;

    int v = gw;
    float4 pt; int cnt; int4 c4;
    if (v < V) {
        pt  = reinterpret_cast<const float4*>(vf)[v * NV_P + lane];
        cnt = vnp[v];
        c4  = reinterpret_cast<const int4*>(coords)[v];
    }
    while (v < V) {
        int vn = v + nw;
        float4 ptn; int cntn; int4 c4n;
        if (vn < V) {   // prefetch next voxel
            ptn  = reinterpret_cast<const float4*>(vf)[vn * NV_P + lane];
            cntn = vnp[vn];
            c4n  = reinterpret_cast<const int4*>(coords)[vn];
        }

        float sx = pt.x, sy = pt.y, sz = pt.z;
        wred3(sx, sy, sz);                    // sum over ALL 32 points (matches ref)
        float inv = 1.0f / (float)cnt;
        float mx = sx * inv, my = sy * inv, mz = sz * inv;
        float cx = (float)c4.w * C_VX + C_XOFF;
        float cy = (float)c4.z * C_VY + C_YOFF;
        float cz = (float)c4.y * C_VZ + C_ZOFF;
        if (lane == 0) {
            g_mc4[v] = make_float4(mx, my, mz, cx);
            g_c2[v]  = make_float2(cy, cz);
        }

        if (lane < cnt) {
            float f[10];
            f[0] = pt.x; f[1] = pt.y; f[2] = pt.z; f[3] = pt.w;
            f[4] = pt.x - mx; f[5] = pt.y - my; f[6] = pt.z - mz;
            f[7] = pt.x - cx; f[8] = pt.y - cy; f[9] = pt.z - cz;
#pragma unroll
            for (int i = 0; i < 10; i++) m[i] += f[i];
            int t = 0;
#pragma unroll
            for (int i = 0; i < 10; i++) {
#pragma unroll
                for (int j = i; j < 10; j++) { S[t] = fmaf(f[i], f[j], S[t]); t++; }
            }
        }
        v = vn; pt = ptn; cnt = cntn; c4 = c4n;
    }

    // warp reduce all 65 accumulators
#pragma unroll
    for (int i = 0; i < 10; i++)
#pragma unroll
        for (int off = 16; off; off >>= 1) m[i] += __shfl_xor_sync(0xffffffffu, m[i], off);
#pragma unroll
    for (int i = 0; i < 55; i++)
#pragma unroll
        for (int off = 16; off; off >>= 1) S[i] += __shfl_xor_sync(0xffffffffu, S[i], off);

    __shared__ float red[NSTAT * 8];
    if (lane == 0) {
#pragma unroll
        for (int i = 0; i < 10; i++) red[i * 8 + wib] = m[i];
#pragma unroll
        for (int i = 0; i < 55; i++) red[(10 + i) * 8 + wib] = S[i];
    }
    __syncthreads();
    int t = threadIdx.x;
    if (t < NSTAT) {
        float s = 0.f;
#pragma unroll
        for (int w = 0; w < 8; w++) s += red[t * 8 + w];
        g_part[t * K1_BLOCKS + blockIdx.x] = s;    // transposed for coalesced kred
    }
}

// ---------------- kred: reduce per-block partials in double ----------------
__global__ void kred_stats() {
    int b = blockIdx.x;                 // one stat per block, NSTAT blocks
    double s = 0.0;
    for (int i = threadIdx.x; i < K1_BLOCKS; i += blockDim.x)
        s += (double)g_part[b * K1_BLOCKS + i];   // coalesced
    __shared__ double sd[256];
    sd[threadIdx.x] = s;
    __syncthreads();
    for (int off = 128; off; off >>= 1) {
        if (threadIdx.x < off) sd[threadIdx.x] += sd[threadIdx.x + off];
        __syncthreads();
    }
    if (threadIdx.x == 0) g_stat[b] = sd[0];
}

// ---------------- k2: fold BN into per-channel a,b ----------------
__global__ void k2_coef(const float* __restrict__ W, const float* __restrict__ gamma,
                        const float* __restrict__ beta, double invN)
{
    int o = threadIdx.x;
    if (o >= 64) return;
    double w[10];
#pragma unroll
    for (int c = 0; c < 10; c++) w[c] = (double)W[o * 10 + c];
    double mean = 0.0;
#pragma unroll
    for (int c = 0; c < 10; c++) mean += w[c] * g_stat[c];
    mean *= invN;
    double e2 = 0.0;
    int t = 0;
#pragma unroll
    for (int i = 0; i < 10; i++) {
#pragma unroll
        for (int j = i; j < 10; j++) {
            double coef = (i == j) ? 1.0 : 2.0;
            e2 += coef * w[i] * w[j] * g_stat[10 + t]; t++;
        }
    }
    e2 *= invN;
    double var = e2 - mean * mean;
    float a = gamma[o] * rsqrtf((float)var + BN_EPS);
    float b = beta[o] - (float)mean * a;
    g_ab[o]      = a;
    g_ab[64 + o] = b;
}

// ---------------- k3: per-voxel max of s*(u.p), epilogue affine+relu ----------------
__global__ __launch_bounds__(K3_THREADS, 4) void k3_out(
    const float* __restrict__ vf, const int* __restrict__ vnp,
    const float* __restrict__ W, float* __restrict__ out, int V)
{
    __shared__ __align__(16) float sh[8 * NV_P * 8];          // 8 warps * 32 pts * 8 floats
    __shared__ unsigned long long sWp[6][32];                 // w-pairs for dims 4..9, per lane
    const int lane = threadIdx.x & 31;
    const int wib  = threadIdx.x >> 5;
    const int gw   = (blockIdx.x * blockDim.x + threadIdx.x) >> 5;
    const int nw   = (gridDim.x * blockDim.x) >> 5;
    float* msh = sh + wib * (NV_P * 8);

    // stage W dim-4..9 channel pairs in shared (saves 12 live regs)
    {
        int t = threadIdx.x;
        if (t < 192) {
            int c = 4 + t / 32, l = t % 32;
            sWp[c - 4][l] = pk2(W[(2 * l) * 10 + c], W[(2 * l + 1) * 10 + c]);
        }
    }

    // lane owns output channels (2*lane, 2*lane+1)
    const int a0 = (2 * lane) * 10, a1 = a0 + 10;
    unsigned long long u0 = add2(add2(pk2(W[a0 + 0], W[a1 + 0]), pk2(W[a0 + 4], W[a1 + 4])), pk2(W[a0 + 7], W[a1 + 7]));
    unsigned long long u1 = add2(add2(pk2(W[a0 + 1], W[a1 + 1]), pk2(W[a0 + 5], W[a1 + 5])), pk2(W[a0 + 8], W[a1 + 8]));
    unsigned long long u2 = add2(add2(pk2(W[a0 + 2], W[a1 + 2]), pk2(W[a0 + 6], W[a1 + 6])), pk2(W[a0 + 9], W[a1 + 9]));
    unsigned long long u3 = pk2(W[a0 + 3], W[a1 + 3]);

    float2 av = reinterpret_cast<const float2*>(g_ab)[lane];
    float2 bv = reinterpret_cast<const float2*>(g_ab + 64)[lane];
    // sign fold: track max of s*x only; out = relu(|a|*M + b)
    float s0 = (av.x >= 0.f) ? 1.f : -1.f;
    float s1 = (av.y >= 0.f) ? 1.f : -1.f;
    unsigned long long spk = pk2(s0, s1);
    u0 = mul2(u0, spk); u1 = mul2(u1, spk); u2 = mul2(u2, spk); u3 = mul2(u3, spk);
    float aax = fabsf(av.x), aay = fabsf(av.y);
    float bvx = bv.x, bvy = bv.y;

    __syncthreads();   // sWp ready

    // depth-1 prefetch pipeline
    int v = gw;
    float4 pt, mc; float2 c2; int cnt;
    if (v < V) {
        pt  = reinterpret_cast<const float4*>(vf)[v * NV_P + lane];
        cnt = vnp[v];
        mc  = g_mc4[v];
        c2  = g_c2[v];
    }
    while (v < V) {
        int vn = v + nw;
        float4 ptn, mcn; float2 c2n; int cntn;
        if (vn < V) {
            ptn  = reinterpret_cast<const float4*>(vf)[vn * NV_P + lane];
            cntn = vnp[vn];
            mcn  = g_mc4[vn];
            c2n  = g_c2[vn];
        }

        // stage duplicated point data: (x,x,y,y),(z,z,w,w) -> broadcast LDS.128 yields f32x2 pairs
        __syncwarp();
        float4* sp = reinterpret_cast<float4*>(msh + lane * 8);
        sp[0] = make_float4(pt.x, pt.x, pt.y, pt.y);
        sp[1] = make_float4(pt.z, pt.z, pt.w, pt.w);
        __syncwarp();

        // base = s * ( -(mean . w[4:7]) - (center . w[7:10]) )  [independent of the loop]
        unsigned long long bt = mul2(pk2(-mc.x, -mc.x), sWp[0][lane]);
        bt = fma2(pk2(-mc.y, -mc.y), sWp[1][lane], bt);
        bt = fma2(pk2(-mc.z, -mc.z), sWp[2][lane], bt);
        bt = fma2(pk2(-mc.w, -mc.w), sWp[3][lane], bt);
        bt = fma2(pk2(-c2.x, -c2.x), sWp[4][lane], bt);
        bt = fma2(pk2(-c2.y, -c2.y), sWp[5][lane], bt);
        unsigned long long base = mul2(bt, spk);

        // single max chain per half over y_p = s*(u . p)
        float mlo = -3.402823466e38f, mhi = -3.402823466e38f;
        const ulonglong2* pp = reinterpret_cast<const ulonglong2*>(msh);
        for (int p = 0; p < cnt; p++) {
            ulonglong2 q = pp[2 * p];       // (x,x),(y,y)
            ulonglong2 r = pp[2 * p + 1];   // (z,z),(w,w)
            unsigned long long acc = mul2(q.x, u0);
            acc = fma2(q.y, u1, acc);
            acc = fma2(r.x, u2, acc);
            acc = fma2(r.y, u3, acc);
            float xlo, xhi; unpk2(acc, xlo, xhi);
            mlo = fmaxf(mlo, xlo); mhi = fmaxf(mhi, xhi);
        }
        float blo, bhi; unpk2(base, blo, bhi);
        float Mlo = mlo + blo;
        float Mhi = mhi + bhi;
        if (cnt < NV_P) { Mlo = fmaxf(Mlo, 0.f); Mhi = fmaxf(Mhi, 0.f); }  // masked rows: raw x = 0
        float r0o = fmaxf(fmaf(aax, Mlo, bvx), 0.f);
        float r1o = fmaxf(fmaf(aay, Mhi, bvy), 0.f);
        reinterpret_cast<float2*>(out)[v * 32 + lane] = make_float2(r0o, r1o);

        v = vn; pt = ptn; cnt = cntn; mc = mcn; c2 = c2n;
    }
}

extern "C" void kernel_launch(void* const* d_in, const int* in_sizes, int n_in,
                              void* d_out, int out_size) {
    const float* vf     = (const float*)d_in[0];
    const int*   vnp    = (const int*)d_in[1];
    const int*   coords = (const int*)d_in[2];
    const float* W      = (const float*)d_in[3];
    const float* gamma  = (const float*)d_in[4];
    const float* beta   = (const float*)d_in[5];
    float* out = (float*)d_out;
    int V = in_sizes[1];   // voxel_num_points element count

    k1_stats<<<K1_BLOCKS, K1_THREADS>>>(vf, vnp, coords, V);
    kred_stats<<<NSTAT, 256>>>();
    double invN = 1.0 / ((double)V * (double)NV_P);
    k2_coef<<<1, 64>>>(W, gamma, beta, invN);
    k3_out<<<K3_BLOCKS, K3_THREADS>>>(vf, vnp, W, out, V);
}

// round 6
// speedup vs baseline: 1.4611x; 1.2057x over previous
#include <cuda_runtime.h>
#include <cstdint>

#define NV_P   32
#define C_VX   0.16f
#define C_VY   0.16f
#define C_VZ   4.0f
#define C_XOFF 0.08f
#define C_YOFF -39.6f
#define C_ZOFF -1.0f
#define BN_EPS 1e-3f

#define K1_BLOCKS 296
#define K1_THREADS 256
#define K3_BLOCKS 444
#define K3_THREADS 256
#define NSTAT 70   // 10 mean (natural) + 60 = 30 packed-S pairs

// -------- global scratch (allocation-free rule: __device__ globals) --------
__device__ float  g_part[NSTAT * K1_BLOCKS];   // transposed: [stat][block] for coalesced kred
__device__ double g_stat[NSTAT];
__device__ float  g_ab[128];                   // a[0..63], b[64..127]
__device__ float4 g_mc4[131072];               // per-voxel (mx,my,mz,cx)
__device__ float2 g_c2[131072];                // per-voxel (cy,cz)

// ---------------- packed f32x2 helpers ----------------
__device__ __forceinline__ unsigned long long pk2(float lo, float hi) {
    unsigned long long r;
    asm("mov.b64 %0, {%1, %2};" : "=l"(r) : "f"(lo), "f"(hi));
    return r;
}
__device__ __forceinline__ void unpk2(unsigned long long x, float& lo, float& hi) {
    asm("mov.b64 {%0, %1}, %2;" : "=f"(lo), "=f"(hi) : "l"(x));
}
__device__ __forceinline__ unsigned long long fma2(unsigned long long a, unsigned long long b, unsigned long long c) {
    unsigned long long d;
    asm("fma.rn.f32x2 %0, %1, %2, %3;" : "=l"(d) : "l"(a), "l"(b), "l"(c));
    return d;
}
__device__ __forceinline__ unsigned long long add2(unsigned long long a, unsigned long long b) {
    unsigned long long d;
    asm("add.rn.f32x2 %0, %1, %2;" : "=l"(d) : "l"(a), "l"(b));
    return d;
}
__device__ __forceinline__ unsigned long long mul2(unsigned long long a, unsigned long long b) {
    unsigned long long d;
    asm("mul.rn.f32x2 %0, %1, %2;" : "=l"(d) : "l"(a), "l"(b));
    return d;
}
__device__ __forceinline__ void wred3(float& a, float& b, float& c) {
#pragma unroll
    for (int off = 16; off; off >>= 1) {
        a += __shfl_xor_sync(0xffffffffu, a, off);
        b += __shfl_xor_sync(0xffffffffu, b, off);
        c += __shfl_xor_sync(0xffffffffu, c, off);
    }
}

// ---------------- k1: packed feature moments, per-block partials, voxel mean/center ----------------
__global__ __launch_bounds__(K1_THREADS, 2) void k1_stats(
    const float* __restrict__ vf, const int* __restrict__ vnp,
    const int* __restrict__ coords, int V)
{
    unsigned long long SP[30];     // packed S: i in 0..9, j2 in i/2..4 -> (f_i*f_{2j2}, f_i*f_{2j2+1})
    unsigned long long mp[5];      // packed m: (f0,f1),(f2,f3),(f4,f5),(f6,f7),(f8,f9)
#pragma unroll
    for (int i = 0; i < 30; i++) SP[i] = 0ull;
#pragma unroll
    for (int i = 0; i < 5; i++) mp[i] = 0ull;

    const int lane = threadIdx.x & 31;
    const int wib  = threadIdx.x >> 5;
    const int gw   = (blockIdx.x * blockDim.x + threadIdx.x) >> 5;
    const int nw   = (gridDim.x * blockDim.x) >> 5;

    // depth-1 prefetch pipeline
    int v = gw;
    float4 pt; int cnt; int4 c4;
    if (v < V) {
        pt  = reinterpret_cast<const float4*>(vf)[v * NV_P + lane];
        cnt = vnp[v];
        c4  = reinterpret_cast<const int4*>(coords)[v];
    }
    while (v < V) {
        int vn = v + nw;
        float4 ptn; int cntn; int4 c4n;
        if (vn < V) {
            ptn  = reinterpret_cast<const float4*>(vf)[vn * NV_P + lane];
            cntn = vnp[vn];
            c4n  = reinterpret_cast<const int4*>(coords)[vn];
        }

        float sx = pt.x, sy = pt.y, sz = pt.z;
        wred3(sx, sy, sz);                    // sum over ALL 32 points (matches ref)
        float inv = 1.0f / (float)cnt;
        float mx = sx * inv, my = sy * inv, mz = sz * inv;
        float cx = (float)c4.w * C_VX + C_XOFF;
        float cy = (float)c4.z * C_VY + C_YOFF;
        float cz = (float)c4.y * C_VZ + C_ZOFF;
        if (lane == 0) {
            g_mc4[v] = make_float4(mx, my, mz, cx);
            g_c2[v]  = make_float2(cy, cz);
        }

        if (lane < cnt) {
            float f0 = pt.x, f1 = pt.y, f2 = pt.z, f3 = pt.w;
            float f4 = pt.x - mx, f5 = pt.y - my, f6 = pt.z - mz;
            float f7 = pt.x - cx, f8 = pt.y - cy, f9 = pt.z - cz;
            unsigned long long g[5];
            g[0] = pk2(f0, f1); g[1] = pk2(f2, f3);
            g[2] = pk2(f4, f5); g[3] = pk2(f6, f7);
            g[4] = pk2(f8, f9);
#pragma unroll
            for (int k = 0; k < 5; k++) mp[k] = add2(mp[k], g[k]);
            float fs[10] = {f0, f1, f2, f3, f4, f5, f6, f7, f8, f9};
            int idx = 0;
#pragma unroll
            for (int i = 0; i < 10; i++) {
                unsigned long long bi = pk2(fs[i], fs[i]);
#pragma unroll
                for (int j2 = i / 2; j2 < 5; j2++) { SP[idx] = fma2(bi, g[j2], SP[idx]); idx++; }
            }
        }
        v = vn; pt = ptn; cnt = cntn; c4 = c4n;
    }

    // warp butterfly on packed accumulators (64-bit shfl)
#pragma unroll
    for (int k = 0; k < 5; k++)
#pragma unroll
        for (int off = 16; off; off >>= 1)
            mp[k] = add2(mp[k], __shfl_xor_sync(0xffffffffu, mp[k], off));
#pragma unroll
    for (int n = 0; n < 30; n++)
#pragma unroll
        for (int off = 16; off; off >>= 1)
            SP[n] = add2(SP[n], __shfl_xor_sync(0xffffffffu, SP[n], off));

    __shared__ float red[8 * NSTAT];
    if (lane == 0) {
#pragma unroll
        for (int k = 0; k < 5; k++) {
            float lo, hi; unpk2(mp[k], lo, hi);
            red[wib * NSTAT + 2 * k] = lo; red[wib * NSTAT + 2 * k + 1] = hi;
        }
#pragma unroll
        for (int n = 0; n < 30; n++) {
            float lo, hi; unpk2(SP[n], lo, hi);
            red[wib * NSTAT + 10 + 2 * n] = lo; red[wib * NSTAT + 10 + 2 * n + 1] = hi;
        }
    }
    __syncthreads();
    int t = threadIdx.x;
    if (t < NSTAT) {
        float s = 0.f;
#pragma unroll
        for (int w = 0; w < 8; w++) s += red[w * NSTAT + t];
        g_part[t * K1_BLOCKS + blockIdx.x] = s;    // transposed for coalesced kred
    }
}

// ---------------- kred: reduce per-block partials in double ----------------
__global__ void kred_stats() {
    int b = blockIdx.x;                 // one stat per block, NSTAT blocks
    double s = 0.0;
    for (int i = threadIdx.x; i < K1_BLOCKS; i += blockDim.x)
        s += (double)g_part[b * K1_BLOCKS + i];   // coalesced
    __shared__ double sd[256];
    sd[threadIdx.x] = s;
    __syncthreads();
    for (int off = 128; off; off >>= 1) {
        if (threadIdx.x < off) sd[threadIdx.x] += sd[threadIdx.x + off];
        __syncthreads();
    }
    if (threadIdx.x == 0) g_stat[b] = sd[0];
}

// ---------------- k2: fold BN into per-channel a,b (dup-aware packed-S coefficients) ----------------
__global__ void k2_coef(const float* __restrict__ W, const float* __restrict__ gamma,
                        const float* __restrict__ beta, double invN)
{
    int o = threadIdx.x;
    if (o >= 64) return;
    double w[10];
#pragma unroll
    for (int c = 0; c < 10; c++) w[c] = (double)W[o * 10 + c];
    double mean = 0.0;
#pragma unroll
    for (int c = 0; c < 10; c++) mean += w[c] * g_stat[c];
    mean *= invN;
    double e2 = 0.0;
    int idx = 0;
#pragma unroll
    for (int i = 0; i < 10; i++) {
#pragma unroll
        for (int j2 = i / 2; j2 < 5; j2++) {
#pragma unroll
            for (int lsel = 0; lsel < 2; lsel++) {
                int j = 2 * j2 + lsel;
                double Sv = g_stat[10 + idx * 2 + lsel];
                // {2k,2k+1} unordered pairs appear twice in the packed set -> coef 1; diag 1; else 2
                double coef = (j == i) ? 1.0 : (((i ^ j) == 1) ? 1.0 : 2.0);
                e2 += coef * w[i] * w[j] * Sv;
            }
            idx++;
        }
    }
    e2 *= invN;
    double var = e2 - mean * mean;
    float a = gamma[o] * rsqrtf((float)var + BN_EPS);
    float b = beta[o] - (float)mean * a;
    g_ab[o]      = a;
    g_ab[64 + o] = b;
}

// ---------------- k3: point-pair packed max of s*(u.p), epilogue affine+relu ----------------
__global__ __launch_bounds__(K3_THREADS, 3) void k3_out(
    const float* __restrict__ vf, const int* __restrict__ vnp,
    const float* __restrict__ W, float* __restrict__ out, int V)
{
    __shared__ __align__(16) float sh[8 * NV_P * 4];   // 8 warps * 16 pairs * 32B = 4KB
    const int lane = threadIdx.x & 31;
    const int wib  = threadIdx.x >> 5;
    const int gw   = (blockIdx.x * blockDim.x + threadIdx.x) >> 5;
    const int nw   = (gridDim.x * blockDim.x) >> 5;
    float* msh = sh + wib * (NV_P * 4);

    // lane owns output channels A=2*lane, B=2*lane+1
    const float* wA = W + (2 * lane) * 10;
    const float* wB = wA + 10;

    float2 av = reinterpret_cast<const float2*>(g_ab)[lane];
    float2 bv = reinterpret_cast<const float2*>(g_ab + 64)[lane];
    float sA = (av.x >= 0.f) ? 1.f : -1.f;
    float sB = (av.y >= 0.f) ? 1.f : -1.f;
    float aax = fabsf(av.x), aay = fabsf(av.y);

    // sign-folded point-packed weights: (u,u) per dim per channel
    float uA0s = sA * (wA[0] + wA[4] + wA[7]);
    float uA1s = sA * (wA[1] + wA[5] + wA[8]);
    float uA2s = sA * (wA[2] + wA[6] + wA[9]);
    float uA3s = sA * wA[3];
    float uB0s = sB * (wB[0] + wB[4] + wB[7]);
    float uB1s = sB * (wB[1] + wB[5] + wB[8]);
    float uB2s = sB * (wB[2] + wB[6] + wB[9]);
    float uB3s = sB * wB[3];
    unsigned long long uA0 = pk2(uA0s, uA0s), uA1 = pk2(uA1s, uA1s);
    unsigned long long uA2 = pk2(uA2s, uA2s), uA3 = pk2(uA3s, uA3s);
    unsigned long long uB0 = pk2(uB0s, uB0s), uB1 = pk2(uB1s, uB1s);
    unsigned long long uB2 = pk2(uB2s, uB2s), uB3 = pk2(uB3s, uB3s);

    // channel-pair packed base weights (dims 4..9), registers
    unsigned long long w4p = pk2(wA[4], wB[4]), w5p = pk2(wA[5], wB[5]);
    unsigned long long w6p = pk2(wA[6], wB[6]), w7p = pk2(wA[7], wB[7]);
    unsigned long long w8p = pk2(wA[8], wB[8]), w9p = pk2(wA[9], wB[9]);

    // depth-1 prefetch pipeline
    int v = gw;
    float4 pt, mc; float2 c2; int cnt;
    if (v < V) {
        pt  = reinterpret_cast<const float4*>(vf)[v * NV_P + lane];
        cnt = vnp[v];
        mc  = g_mc4[v];
        c2  = g_c2[v];
    }
    while (v < V) {
        int vn = v + nw;
        float4 ptn, mcn; float2 c2n; int cntn;
        if (vn < V) {
            ptn  = reinterpret_cast<const float4*>(vf)[vn * NV_P + lane];
            cntn = vnp[vn];
            mcn  = g_mc4[vn];
            c2n  = g_c2[vn];
        }

        // stage pair-transposed point data: pair k at 32B offset k*32:
        //   [x_{2k},x_{2k+1},y_{2k},y_{2k+1}] , [z_{2k},z_{2k+1},w_{2k},w_{2k+1}]
        // lane writes 16B at msh+16*lane (contiguous, conflict-free)
        __syncwarp();
        {
            float px = __shfl_xor_sync(0xffffffffu, pt.x, 1);
            float py = __shfl_xor_sync(0xffffffffu, pt.y, 1);
            float pz = __shfl_xor_sync(0xffffffffu, pt.z, 1);
            float pw = __shfl_xor_sync(0xffffffffu, pt.w, 1);
            float4 st;
            if (lane & 1) st = make_float4(pz, pt.z, pw, pt.w);   // second half of pair
            else          st = make_float4(pt.x, px, pt.y, py);   // first half of pair
            reinterpret_cast<float4*>(msh)[lane] = st;
        }
        __syncwarp();

        // base (channel-pair packed): -(mean . w[4:7]) - (center . w[7:10])
        unsigned long long bt = mul2(pk2(-mc.x, -mc.x), w4p);
        bt = fma2(pk2(-mc.y, -mc.y), w5p, bt);
        bt = fma2(pk2(-mc.z, -mc.z), w6p, bt);
        bt = fma2(pk2(-mc.w, -mc.w), w7p, bt);
        bt = fma2(pk2(-c2.x, -c2.x), w8p, bt);
        bt = fma2(pk2(-c2.y, -c2.y), w9p, bt);
        float blo, bhi; unpk2(bt, blo, bhi);
        float baseA = sA * blo, baseB = sB * bhi;

        // max over points of s*(u . p), two points per iteration
        float mA = -3.402823466e38f, mB = -3.402823466e38f;
        const ulonglong2* pp = reinterpret_cast<const ulonglong2*>(msh);
        int npair = cnt >> 1;
        for (int k = 0; k < npair; k++) {
            ulonglong2 q = pp[2 * k];       // (x0,x1),(y0,y1)
            ulonglong2 r = pp[2 * k + 1];   // (z0,z1),(w0,w1)
            unsigned long long aA = mul2(q.x, uA0);
            unsigned long long aB = mul2(q.x, uB0);
            aA = fma2(q.y, uA1, aA);  aB = fma2(q.y, uB1, aB);
            aA = fma2(r.x, uA2, aA);  aB = fma2(r.x, uB2, aB);
            aA = fma2(r.y, uA3, aA);  aB = fma2(r.y, uB3, aB);
            float t0, t1;
            unpk2(aA, t0, t1); mA = fmaxf(mA, fmaxf(t0, t1));
            unpk2(aB, t0, t1); mB = fmaxf(mB, fmaxf(t0, t1));
        }
        if (cnt & 1) {   // odd count: last pair, low half only
            ulonglong2 q = pp[2 * npair];
            ulonglong2 r = pp[2 * npair + 1];
            unsigned long long aA = mul2(q.x, uA0);
            unsigned long long aB = mul2(q.x, uB0);
            aA = fma2(q.y, uA1, aA);  aB = fma2(q.y, uB1, aB);
            aA = fma2(r.x, uA2, aA);  aB = fma2(r.x, uB2, aB);
            aA = fma2(r.y, uA3, aA);  aB = fma2(r.y, uB3, aB);
            float t0, t1;
            unpk2(aA, t0, t1); mA = fmaxf(mA, t0);
            unpk2(aB, t0, t1); mB = fmaxf(mB, t0);
        }

        float xA = mA + baseA;
        float xB = mB + baseB;
        if (cnt < NV_P) { xA = fmaxf(xA, 0.f); xB = fmaxf(xB, 0.f); }  // masked rows: raw x = 0
        float r0o = fmaxf(fmaf(aax, xA, bv.x), 0.f);
        float r1o = fmaxf(fmaf(aay, xB, bv.y), 0.f);
        reinterpret_cast<float2*>(out)[v * 32 + lane] = make_float2(r0o, r1o);

        v = vn; pt = ptn; cnt = cntn; mc = mcn; c2 = c2n;
    }
}

extern "C" void kernel_launch(void* const* d_in, const int* in_sizes, int n_in,
                              void* d_out, int out_size) {
    const float* vf     = (const float*)d_in[0];
    const int*   vnp    = (const int*)d_in[1];
    const int*   coords = (const int*)d_in[2];
    const float* W      = (const float*)d_in[3];
    const float* gamma  = (const float*)d_in[4];
    const float* beta   = (const float*)d_in[5];
    float* out = (float*)d_out;
    int V = in_sizes[1];   // voxel_num_points element count

    k1_stats<<<K1_BLOCKS, K1_THREADS>>>(vf, vnp, coords, V);
    kred_stats<<<NSTAT, 256>>>();
    double invN = 1.0 / ((double)V * (double)NV_P);
    k2_coef<<<1, 64>>>(W, gamma, beta, invN);
    k3_out<<<K3_BLOCKS, K3_THREADS>>>(vf, vnp, W, out, V);
}

// round 7
// speedup vs baseline: 1.5142x; 1.0363x over previous
#include <cuda_runtime.h>
#include <cstdint>

#define NV_P   32
#define C_VX   0.16f
#define C_VY   0.16f
#define C_VZ   4.0f
#define C_XOFF 0.08f
#define C_YOFF -39.6f
#define C_ZOFF -1.0f
#define BN_EPS 1e-3f

#define KF_BLOCKS 304
#define KF_THREADS 256
#define NSTAT 70   // 10 mean (natural) + 60 = 30 packed-S pairs

// -------- global scratch (allocation-free rule: __device__ globals) --------
__device__ float  g_part[NSTAT * KF_BLOCKS];   // transposed: [stat][block] for coalesced kred
__device__ double g_stat[NSTAT];
__device__ float  g_ab[128];                   // |a|[0..63], b[64..127]

// ---------------- packed f32x2 helpers ----------------
__device__ __forceinline__ unsigned long long pk2(float lo, float hi) {
    unsigned long long r;
    asm("mov.b64 %0, {%1, %2};" : "=l"(r) : "f"(lo), "f"(hi));
    return r;
}
__device__ __forceinline__ void unpk2(unsigned long long x, float& lo, float& hi) {
    asm("mov.b64 {%0, %1}, %2;" : "=f"(lo), "=f"(hi) : "l"(x));
}
__device__ __forceinline__ unsigned long long fma2(unsigned long long a, unsigned long long b, unsigned long long c) {
    unsigned long long d;
    asm("fma.rn.f32x2 %0, %1, %2, %3;" : "=l"(d) : "l"(a), "l"(b), "l"(c));
    return d;
}
__device__ __forceinline__ unsigned long long add2(unsigned long long a, unsigned long long b) {
    unsigned long long d;
    asm("add.rn.f32x2 %0, %1, %2;" : "=l"(d) : "l"(a), "l"(b));
    return d;
}
__device__ __forceinline__ unsigned long long mul2(unsigned long long a, unsigned long long b) {
    unsigned long long d;
    asm("mul.rn.f32x2 %0, %1, %2;" : "=l"(d) : "l"(a), "l"(b));
    return d;
}
__device__ __forceinline__ void wred3(float& a, float& b, float& c) {
#pragma unroll
    for (int off = 16; off; off >>= 1) {
        a += __shfl_xor_sync(0xffffffffu, a, off);
        b += __shfl_xor_sync(0xffffffffu, b, off);
        c += __shfl_xor_sync(0xffffffffu, c, off);
    }
}

// ---------------- kF: fused stats + signed-max pass (single read of vf) ----------------
__global__ __launch_bounds__(KF_THREADS, 2) void kF_fused(
    const float* __restrict__ vf, const int* __restrict__ vnp,
    const int* __restrict__ coords, const float* __restrict__ W,
    const float* __restrict__ gamma, float* __restrict__ out, int V)
{
    __shared__ __align__(16) float sh[8 * NV_P * 4];   // 8 warps * 16 pairs * 32B = 4KB staging
    __shared__ unsigned long long sWp[6][32];          // base weights dims 4..9, channel-pair packed

    const int lane = threadIdx.x & 31;
    const int wib  = threadIdx.x >> 5;
    const int gw   = (blockIdx.x * blockDim.x + threadIdx.x) >> 5;
    const int nw   = (gridDim.x * blockDim.x) >> 5;
    float* msh = sh + wib * (NV_P * 4);

    // stage base weights (dims 4..9) channel-pair packed in shared
    {
        int t = threadIdx.x;
        if (t < 192) {
            int c = 4 + t / 32, l = t % 32;
            sWp[c - 4][l] = pk2(W[(2 * l) * 10 + c], W[(2 * l + 1) * 10 + c]);
        }
    }

    // lane owns output channels A=2*lane, B=2*lane+1; sign from gamma (rsqrt>0 => sign(a)=sign(gamma))
    const float* wA = W + (2 * lane) * 10;
    const float* wB = wA + 10;
    float sA = (gamma[2 * lane]     >= 0.f) ? 1.f : -1.f;
    float sB = (gamma[2 * lane + 1] >= 0.f) ? 1.f : -1.f;
    float uA0s = sA * (wA[0] + wA[4] + wA[7]);
    float uA1s = sA * (wA[1] + wA[5] + wA[8]);
    float uA2s = sA * (wA[2] + wA[6] + wA[9]);
    float uA3s = sA * wA[3];
    float uB0s = sB * (wB[0] + wB[4] + wB[7]);
    float uB1s = sB * (wB[1] + wB[5] + wB[8]);
    float uB2s = sB * (wB[2] + wB[6] + wB[9]);
    float uB3s = sB * wB[3];
    unsigned long long uA0 = pk2(uA0s, uA0s), uA1 = pk2(uA1s, uA1s);
    unsigned long long uA2 = pk2(uA2s, uA2s), uA3 = pk2(uA3s, uA3s);
    unsigned long long uB0 = pk2(uB0s, uB0s), uB1 = pk2(uB1s, uB1s);
    unsigned long long uB2 = pk2(uB2s, uB2s), uB3 = pk2(uB3s, uB3s);

    // stats accumulators (packed)
    unsigned long long SP[30];
    unsigned long long mp[5];
#pragma unroll
    for (int i = 0; i < 30; i++) SP[i] = 0ull;
#pragma unroll
    for (int i = 0; i < 5; i++) mp[i] = 0ull;

    __syncthreads();   // sWp ready

    // depth-1 prefetch pipeline
    int v = gw;
    float4 pt; int cnt; int4 c4;
    if (v < V) {
        pt  = reinterpret_cast<const float4*>(vf)[v * NV_P + lane];
        cnt = vnp[v];
        c4  = reinterpret_cast<const int4*>(coords)[v];
    }
    while (v < V) {
        int vn = v + nw;
        float4 ptn; int cntn; int4 c4n;
        if (vn < V) {
            ptn  = reinterpret_cast<const float4*>(vf)[vn * NV_P + lane];
            cntn = vnp[vn];
            c4n  = reinterpret_cast<const int4*>(coords)[vn];
        }

        // per-voxel mean (sum over ALL 32 points, matches ref) and center
        float sx = pt.x, sy = pt.y, sz = pt.z;
        wred3(sx, sy, sz);
        float inv = 1.0f / (float)cnt;
        float mx = sx * inv, my = sy * inv, mz = sz * inv;
        float cx = (float)c4.w * C_VX + C_XOFF;
        float cy = (float)c4.z * C_VY + C_YOFF;
        float cz = (float)c4.y * C_VZ + C_ZOFF;

        // ---- stats body (lane = point index) ----
        if (lane < cnt) {
            float f0 = pt.x, f1 = pt.y, f2 = pt.z, f3 = pt.w;
            float f4 = pt.x - mx, f5 = pt.y - my, f6 = pt.z - mz;
            float f7 = pt.x - cx, f8 = pt.y - cy, f9 = pt.z - cz;
            unsigned long long g[5];
            g[0] = pk2(f0, f1); g[1] = pk2(f2, f3);
            g[2] = pk2(f4, f5); g[3] = pk2(f6, f7);
            g[4] = pk2(f8, f9);
#pragma unroll
            for (int k = 0; k < 5; k++) mp[k] = add2(mp[k], g[k]);
            float fs[10] = {f0, f1, f2, f3, f4, f5, f6, f7, f8, f9};
            int idx = 0;
#pragma unroll
            for (int i = 0; i < 10; i++) {
                unsigned long long bi = pk2(fs[i], fs[i]);
#pragma unroll
                for (int j2 = i / 2; j2 < 5; j2++) { SP[idx] = fma2(bi, g[j2], SP[idx]); idx++; }
            }
        }

        // ---- stage pair-transposed point data for the max loop ----
        __syncwarp();
        {
            float px = __shfl_xor_sync(0xffffffffu, pt.x, 1);
            float py = __shfl_xor_sync(0xffffffffu, pt.y, 1);
            float pz = __shfl_xor_sync(0xffffffffu, pt.z, 1);
            float pw = __shfl_xor_sync(0xffffffffu, pt.w, 1);
            float4 st;
            if (lane & 1) st = make_float4(pz, pt.z, pw, pt.w);
            else          st = make_float4(pt.x, px, pt.y, py);
            reinterpret_cast<float4*>(msh)[lane] = st;
        }
        __syncwarp();

        // base (channel-pair packed from shared): -(mean . w[4:7]) - (center . w[7:10])
        unsigned long long bt = mul2(pk2(-mx, -mx), sWp[0][lane]);
        bt = fma2(pk2(-my, -my), sWp[1][lane], bt);
        bt = fma2(pk2(-mz, -mz), sWp[2][lane], bt);
        bt = fma2(pk2(-cx, -cx), sWp[3][lane], bt);
        bt = fma2(pk2(-cy, -cy), sWp[4][lane], bt);
        bt = fma2(pk2(-cz, -cz), sWp[5][lane], bt);
        float blo, bhi; unpk2(bt, blo, bhi);
        float baseA = sA * blo, baseB = sB * bhi;

        // ---- max over points of s*(u . p), two points per iteration ----
        float mA = -3.402823466e38f, mB = -3.402823466e38f;
        const ulonglong2* pp = reinterpret_cast<const ulonglong2*>(msh);
        int npair = cnt >> 1;
        for (int k = 0; k < npair; k++) {
            ulonglong2 q = pp[2 * k];       // (x0,x1),(y0,y1)
            ulonglong2 r = pp[2 * k + 1];   // (z0,z1),(w0,w1)
            unsigned long long aA = mul2(q.x, uA0);
            unsigned long long aB = mul2(q.x, uB0);
            aA = fma2(q.y, uA1, aA);  aB = fma2(q.y, uB1, aB);
            aA = fma2(r.x, uA2, aA);  aB = fma2(r.x, uB2, aB);
            aA = fma2(r.y, uA3, aA);  aB = fma2(r.y, uB3, aB);
            float t0, t1;
            unpk2(aA, t0, t1); mA = fmaxf(mA, fmaxf(t0, t1));
            unpk2(aB, t0, t1); mB = fmaxf(mB, fmaxf(t0, t1));
        }
        if (cnt & 1) {   // odd count: low half of last pair only
            ulonglong2 q = pp[2 * npair];
            ulonglong2 r = pp[2 * npair + 1];
            unsigned long long aA = mul2(q.x, uA0);
            unsigned long long aB = mul2(q.x, uB0);
            aA = fma2(q.y, uA1, aA);  aB = fma2(q.y, uB1, aB);
            aA = fma2(r.x, uA2, aA);  aB = fma2(r.x, uB2, aB);
            aA = fma2(r.y, uA3, aA);  aB = fma2(r.y, uB3, aB);
            float t0, t1;
            unpk2(aA, t0, t1); mA = fmaxf(mA, t0);
            unpk2(aB, t0, t1); mB = fmaxf(mB, t0);
        }

        float xA = mA + baseA;
        float xB = mB + baseB;
        if (cnt < NV_P) { xA = fmaxf(xA, 0.f); xB = fmaxf(xB, 0.f); }  // masked rows: raw x = 0
        reinterpret_cast<float2*>(out)[v * 32 + lane] = make_float2(xA, xB);  // pre-affine raw

        v = vn; pt = ptn; cnt = cntn; c4 = c4n;
    }

    // ---- reduce stats: warp butterfly then cross-warp via shared ----
#pragma unroll
    for (int k = 0; k < 5; k++)
#pragma unroll
        for (int off = 16; off; off >>= 1)
            mp[k] = add2(mp[k], __shfl_xor_sync(0xffffffffu, mp[k], off));
#pragma unroll
    for (int n = 0; n < 30; n++)
#pragma unroll
        for (int off = 16; off; off >>= 1)
            SP[n] = add2(SP[n], __shfl_xor_sync(0xffffffffu, SP[n], off));

    __shared__ float red[8 * NSTAT];
    if (lane == 0) {
#pragma unroll
        for (int k = 0; k < 5; k++) {
            float lo, hi; unpk2(mp[k], lo, hi);
            red[wib * NSTAT + 2 * k] = lo; red[wib * NSTAT + 2 * k + 1] = hi;
        }
#pragma unroll
        for (int n = 0; n < 30; n++) {
            float lo, hi; unpk2(SP[n], lo, hi);
            red[wib * NSTAT + 10 + 2 * n] = lo; red[wib * NSTAT + 10 + 2 * n + 1] = hi;
        }
    }
    __syncthreads();
    int t = threadIdx.x;
    if (t < NSTAT) {
        float s = 0.f;
#pragma unroll
        for (int w = 0; w < 8; w++) s += red[w * NSTAT + t];
        g_part[t * KF_BLOCKS + blockIdx.x] = s;
    }
}

// ---------------- kred: reduce per-block partials in double ----------------
__global__ void kred_stats() {
    int b = blockIdx.x;
    double s = 0.0;
    for (int i = threadIdx.x; i < KF_BLOCKS; i += blockDim.x)
        s += (double)g_part[b * KF_BLOCKS + i];
    __shared__ double sd[256];
    sd[threadIdx.x] = s;
    __syncthreads();
    for (int off = 128; off; off >>= 1) {
        if (threadIdx.x < off) sd[threadIdx.x] += sd[threadIdx.x + off];
        __syncthreads();
    }
    if (threadIdx.x == 0) g_stat[b] = sd[0];
}

// ---------------- k2: fold BN into |a|, b ----------------
__global__ void k2_coef(const float* __restrict__ W, const float* __restrict__ gamma,
                        const float* __restrict__ beta, double invN)
{
    int o = threadIdx.x;
    if (o >= 64) return;
    double w[10];
#pragma unroll
    for (int c = 0; c < 10; c++) w[c] = (double)W[o * 10 + c];
    double mean = 0.0;
#pragma unroll
    for (int c = 0; c < 10; c++) mean += w[c] * g_stat[c];
    mean *= invN;
    double e2 = 0.0;
    int idx = 0;
#pragma unroll
    for (int i = 0; i < 10; i++) {
#pragma unroll
        for (int j2 = i / 2; j2 < 5; j2++) {
#pragma unroll
            for (int lsel = 0; lsel < 2; lsel++) {
                int j = 2 * j2 + lsel;
                double Sv = g_stat[10 + idx * 2 + lsel];
                // {2k,2k+1} pairs appear twice in packed set -> coef 1; diag 1; else 2
                double coef = (j == i) ? 1.0 : (((i ^ j) == 1) ? 1.0 : 2.0);
                e2 += coef * w[i] * w[j] * Sv;
            }
            idx++;
        }
    }
    e2 *= invN;
    double var = e2 - mean * mean;
    float a = gamma[o] * rsqrtf((float)var + BN_EPS);
    float b = beta[o] - (float)mean * a;
    g_ab[o]      = fabsf(a);                 // kF already folded sign(a)=sign(gamma)
    g_ab[64 + o] = b;
}

// ---------------- kE: elementwise out = relu(|a|*raw + b), in place ----------------
__global__ __launch_bounds__(256) void kE_epi(float* __restrict__ out, int n4)
{
    int t = blockIdx.x * blockDim.x + threadIdx.x;
    if (t >= n4) return;
    int ch = (t * 4) & 63;                                   // 4 consecutive channels, 16-aligned
    float4 a4 = *reinterpret_cast<const float4*>(g_ab + ch);
    float4 b4 = *reinterpret_cast<const float4*>(g_ab + 64 + ch);
    float4 r = reinterpret_cast<float4*>(out)[t];
    r.x = fmaxf(fmaf(a4.x, r.x, b4.x), 0.f);
    r.y = fmaxf(fmaf(a4.y, r.y, b4.y), 0.f);
    r.z = fmaxf(fmaf(a4.z, r.z, b4.z), 0.f);
    r.w = fmaxf(fmaf(a4.w, r.w, b4.w), 0.f);
    reinterpret_cast<float4*>(out)[t] = r;
}

extern "C" void kernel_launch(void* const* d_in, const int* in_sizes, int n_in,
                              void* d_out, int out_size) {
    const float* vf     = (const float*)d_in[0];
    const int*   vnp    = (const int*)d_in[1];
    const int*   coords = (const int*)d_in[2];
    const float* W      = (const float*)d_in[3];
    const float* gamma  = (const float*)d_in[4];
    const float* beta   = (const float*)d_in[5];
    float* out = (float*)d_out;
    int V = in_sizes[1];   // voxel_num_points element count

    kF_fused<<<KF_BLOCKS, KF_THREADS>>>(vf, vnp, coords, W, gamma, out, V);
    kred_stats<<<NSTAT, 256>>>();
    double invN = 1.0 / ((double)V * (double)NV_P);
    k2_coef<<<1, 64>>>(W, gamma, beta, invN);
    int n4 = out_size / 4;
    kE_epi<<<(n4 + 255) / 256, 256>>>(out, n4);
}